// round 17
// baseline (speedup 1.0000x reference)
#include <cuda_runtime.h>

#define BB 32
#define TT 2048
#define CC 2048
#define EE 64
#define SEG 16
#define TCHUNK (TT / SEG)          // 128
#define C4 (CC / 4)                // 512
#define E4N (EE / 4)               // 16
#define TQ 128                     // t-rows per fused block (grid (32,16))
#define PARTS 16
#define CPART (CC / PARTS)         // 128

#define BTE (BB * TT * EE)         // 4194304 = 2^22
#define FB_OFF  BTE                // 4194304
#define LOG_OFF (BTE + 1)          // 4194305
#define MASK_OFF (BTE + 1 + BB * EE) // 4196353 (== 1 mod 4)

// Scratch (no cudaMalloc allowed)
__device__ float g_partials[SEG * BB * CC];   // 2 MB
__device__ float g_dots[BB * PARTS * EE];     // 128 KB
__device__ float g_ssum[BB * PARTS * EE];     // 128 KB
__device__ float g_sumsq[BB * PARTS];
__device__ __align__(16) float g_probs_seq[BB * EE];
__device__ __align__(16) float g_mask_seq[BB * EE];
__device__ int   g_cnt[BB];
__device__ volatile int g_flag[BB];

// ---------------------------------------------------------------------------
// Kernel 1: partial sums of hidden_states over T (round-8 verbatim, measured
// 80us @ 85% DRAM = HBM cap). Zeroes counters/flags/FB slot; the kernel
// boundary publishes them before k2 runs.
// ---------------------------------------------------------------------------
__global__ void k1_partial_sums(const float* __restrict__ hs, float* __restrict__ out) {
    if (blockIdx.x == 0 && blockIdx.y == 0 && blockIdx.z == 0) {
        if (threadIdx.x == 0) out[FB_OFF] = 0.0f;
        if (threadIdx.x < BB) { g_cnt[threadIdx.x] = 0; g_flag[threadIdx.x] = 0; }
    }

    const int c4  = blockIdx.x * 256 + threadIdx.x;   // 0..511
    const int b   = blockIdx.y;
    const int seg = blockIdx.z;

    const float4* __restrict__ hs4 = (const float4*)hs;
    size_t base = ((size_t)b * TT + (size_t)seg * TCHUNK) * C4 + (size_t)c4;

    float4 acc = make_float4(0.f, 0.f, 0.f, 0.f);
#pragma unroll 8
    for (int t = 0; t < TCHUNK; ++t) {
        float4 v = hs4[base + (size_t)t * C4];
        acc.x += v.x; acc.y += v.y; acc.z += v.z; acc.w += v.w;
    }
    ((float4*)g_partials)[((size_t)seg * BB + b) * C4 + c4] = acc;
}

// ---------------------------------------------------------------------------
// Kernel 2: fused stage-1 + elected finish + broadcast.
// grid = (BB, PARTS) = (32,16) = 512 blocks x 256 threads, >=4 CTAs/SM forced
// -> all blocks wave-1 resident -> the flag wait is deadlock-free.
// Block (b, part):
//   1. stage-1 reduction for its 128-c chunk (round-8 k2a code).
//   2. atomic election; the 16th-arriving block for b finishes the gating
//      (round-8 producer code: fixed-order sums -> deterministic), writes
//      probs/mask/logits/fallback, raises g_flag[b].
//   3. all 16 blocks broadcast their TQ=128-row chunk (round-8 store pattern).
// ALIGNMENT FIX vs round 15: all smem arrays that are read as float4 carry
// __align__(16), and scalar smem cells are declared AFTER the arrays (the
// round-15 crash was probs_s landing at offset ==4 mod 16 after `int s_last`).
// ---------------------------------------------------------------------------
__global__ void __launch_bounds__(256, 4)
k2_fused(const float* __restrict__ sim, const float* __restrict__ gates,
         float* __restrict__ out) {
    __shared__ __align__(16) float rep_s[CPART];
    __shared__ __align__(16) float red[128];
    __shared__ __align__(16) float dots4[4][EE];
    __shared__ __align__(16) float ss4[4][EE];
    __shared__ __align__(16) float logits_s[EE];
    __shared__ __align__(16) float msk[EE];
    __shared__ __align__(16) float probs_s[EE];
    __shared__ int   s_last;
    __shared__ float sm_nrep, sm_max, sm_sum;

    const int b    = blockIdx.x;
    const int part = blockIdx.y;
    const int tid  = threadIdx.x;
    const int c0   = part * CPART;

    // ==================== stage 1 (round-8 k2a) ====================
    if (tid < CPART) {
        float s = 0.f;
#pragma unroll
        for (int p = 0; p < SEG; ++p)
            s += g_partials[(size_t)p * BB * CC + (size_t)b * CC + c0 + tid];
        float r = s * (1.0f / TT);
        rep_s[tid] = r;
        red[tid] = r * r;
    }
    __syncthreads();
    for (int ofs = 64; ofs > 0; ofs >>= 1) {
        if (tid < ofs) red[tid] += red[tid + ofs];
        __syncthreads();
    }
    if (tid == 0) g_sumsq[b * PARTS + part] = red[0];

    // partial dot/ss over this c-chunk: e = tid&63, 4 c-groups of 32
    {
        const int e  = tid & (EE - 1);
        const int cg = tid >> 6;
        float dot = 0.f, ss = 0.f;
#pragma unroll 8
        for (int j = 0; j < 32; ++j) {
            int cl = cg * 32 + j;
            float sv = sim[(size_t)(c0 + cl) * EE + e];
            dot = fmaf(rep_s[cl], sv, dot);
            ss  = fmaf(sv, sv, ss);
        }
        dots4[cg][e] = dot;
        ss4[cg][e]  = ss;
    }
    __syncthreads();

    if (tid < EE) {
        g_dots[(size_t)(b * PARTS + part) * EE + tid] =
            dots4[0][tid] + dots4[1][tid] + dots4[2][tid] + dots4[3][tid];
        g_ssum[(size_t)(b * PARTS + part) * EE + tid] =
            ss4[0][tid] + ss4[1][tid] + ss4[2][tid] + ss4[3][tid];
    }

    // ==================== election ====================
    __threadfence();             // release stage-1 results
    __syncthreads();
    if (tid == 0) s_last = (atomicAdd(&g_cnt[b], 1) == PARTS - 1) ? 1 : 0;
    __syncthreads();

    if (s_last) {
        // ============ finish (round-8 producer, one block per b) ============
        __threadfence();         // acquire all 16 partials
        if (tid == 0) {
            float s = 0.f;
#pragma unroll
            for (int p = 0; p < PARTS; ++p) s += g_sumsq[b * PARTS + p];
            sm_nrep = sqrtf(s);
        }
        float l = 0.f;
        if (tid < EE) {
            float dot = 0.f, ss = 0.f;
#pragma unroll
            for (int p = 0; p < PARTS; ++p) {
                dot += g_dots[(size_t)(b * PARTS + p) * EE + tid];
                ss  += g_ssum[(size_t)(b * PARTS + p) * EE + tid];
            }
            __syncthreads();     // sm_nrep ready
            float nrep = fmaxf(sm_nrep, 1e-12f);
            float ncol = fmaxf(sqrtf(ss), 1e-12f);
            float aff  = dot / (nrep * ncol);
            float gv   = gates[tid];
            float sig  = 1.0f / (1.0f + __expf(-gv));
            l = aff - sig;
            logits_s[tid] = l;
        } else {
            __syncthreads();
        }

        const int na = __syncthreads_count((tid < EE) && (l > 0.f));
        const int inactive = (na == 0) ? 1 : 0;

        // mask: threshold or top-32 fallback (lax.top_k tie semantics:
        // stable, lowest index wins among equals)
        if (tid < EE) {
            float m;
            if (!inactive) {
                m = (l > 0.f) ? 1.f : 0.f;
            } else {
                int rank = 0;
                for (int j = 0; j < EE; ++j) {
                    float lj = logits_s[j];
                    rank += ((lj > l) || (lj == l && j < tid)) ? 1 : 0;
                }
                m = (rank < (EE / 2)) ? 1.f : 0.f;
            }
            msk[tid] = m;
        }
        __syncthreads();

        if (tid == 0) {
            float mx = -3.402823466e+38f;
            for (int e = 0; e < EE; ++e)
                if (msk[e] > 0.f) mx = fmaxf(mx, fmaxf(logits_s[e], 0.f));
            float sum = 0.f;
            for (int e = 0; e < EE; ++e)
                if (msk[e] > 0.f) sum += __expf(fmaxf(logits_s[e], 0.f) - mx);
            sm_max = mx;
            sm_sum = sum;
            if (inactive) atomicAdd(&out[FB_OFF], 1.0f);  // integer-valued -> deterministic
        }
        __syncthreads();

        if (tid < EE) {
            float gated = fmaxf(l, 0.f);
            float p = (msk[tid] > 0.f) ? (__expf(gated - sm_max) / sm_sum) : 0.f;
            probs_s[tid] = p;
            g_probs_seq[b * EE + tid] = p;
            g_mask_seq[b * EE + tid]  = msk[tid];
            out[LOG_OFF + b * EE + tid] = l;
        }
        __threadfence();
        __syncthreads();
        if (tid == 0) g_flag[b] = 1;
        __syncthreads();
        // probs_s / msk already in smem
    } else {
        // ============ brief wait for this b's finisher ============
        if (tid == 0) {
            while (g_flag[b] == 0) { __nanosleep(64); }
        }
        __syncthreads();
        __threadfence();         // acquire finisher's writes
        if (tid < EE) {
            probs_s[tid] = g_probs_seq[b * EE + tid];
            msk[tid]     = g_mask_seq[b * EE + tid];
        }
        __syncthreads();
    }

    // ========== broadcast chunk [part*TQ, part*TQ+TQ) (round-8 pattern) ====
    const int slot = tid & 15;   // 0..15
    const int trow = tid >> 4;   // 0..15

    const float4 pv = ((const float4*)probs_s)[slot];   // probs_s is 16B-aligned

    // mask values per slot: slot 0 -> scalars e=0,1,2,63 ; slot s>0 ->
    // aligned float4 at e=4s-1 (MASK_OFF == 1 mod 4)
    float4 mv = make_float4(0.f, 0.f, 0.f, 0.f);
    float m0 = 0.f, m1 = 0.f, m2 = 0.f, m63 = 0.f;
    if (slot == 0) { m0 = msk[0]; m1 = msk[1]; m2 = msk[2]; m63 = msk[63]; }
    else { int e = 4 * slot - 1; mv = make_float4(msk[e], msk[e+1], msk[e+2], msk[e+3]); }

    const size_t brow = (size_t)b * TT * EE;
    const int t0 = part * TQ;

#pragma unroll
    for (int it = 0; it < TQ / 16; ++it) {
        const size_t row = brow + (size_t)(t0 + it * 16 + trow) * EE;
        __stcs((float4*)(out) + row / 4 + slot, pv);
        if (slot == 0) {
            float* d = out + MASK_OFF + row;
            __stcs(d + 0, m0); __stcs(d + 1, m1); __stcs(d + 2, m2); __stcs(d + 63, m63);
        } else {
            __stcs((float4*)(out + MASK_OFF + row + 4 * slot - 1), mv);
        }
    }
}

// ---------------------------------------------------------------------------
extern "C" void kernel_launch(void* const* d_in, const int* in_sizes, int n_in,
                              void* d_out, int out_size) {
    const float* hs    = (const float*)d_in[0];
    const float* sim   = (const float*)d_in[1];
    const float* gates = (const float*)d_in[2];
    float* out = (float*)d_out;

    k1_partial_sums<<<dim3(C4 / 256, BB, SEG), 256>>>(hs, out);
    k2_fused<<<dim3(BB, PARTS), 256>>>(sim, gates, out);
}